// round 12
// baseline (speedup 1.0000x reference)
#include <cuda_runtime.h>

// loss = 0.5 * ( sum_j ( (y-mu)^2/sigma + log(sigma) ) + NT*log(2*pi) ) / (NT*BS)
// over the LAST row only (reference selects log_prob[-1]).
//
// R11: full 16-element division folding per thread.
//   Sum_i d_i^2/s_i over 16 elems = num16 / p16  (common-denominator tree),
//   and sum(log s_i) = log(p16)  -> ONE __fdividef + ONE __logf per thread
//   (2 MUFU ops, was 10). Extra FMULs land on the idle FMA pipe.
// 4 warps (one per SMSP), 12 front-batched LDG.128/thread, LDS.128 tail (R10).
//
// sigma in [0.1,1.1] => p16 in [1e-16, 4.6]: fp32-normal range, safe.

#define BS 4096
#define NT 2048
#define THREADS 128          // 128 threads * 16 floats = 2048 = NT

__global__ void __launch_bounds__(THREADS, 1)
criterion_last_row_kernel(const float* __restrict__ mu,
                          const float* __restrict__ sigma,
                          const float* __restrict__ ty,
                          float* __restrict__ out) {
    const long long base = (long long)(BS - 1) * NT;
    const int tid = threadIdx.x;

    const float4* m4p = reinterpret_cast<const float4*>(mu + base);
    const float4* s4p = reinterpret_cast<const float4*>(sigma + base);
    const float4* y4p = reinterpret_cast<const float4*>(ty + base);

    // 4 float4 groups per array; all 12 loads independent (front-batched MLP).
    float4 m[4], s[4], y[4];
    #pragma unroll
    for (int g = 0; g < 4; g++) {
        m[g] = m4p[tid + g * THREADS];
        s[g] = s4p[tid + g * THREADS];
        y[g] = y4p[tid + g * THREADS];
    }

    // Per-4-group numerator/denominator (pairwise fold, as R5):
    //   num4 = (dx^2*sy + dy^2*sx)*pzw + (dz^2*sw + dw^2*sz)*pxy
    //   p4   = pxy * pzw
    float num4[4], p4[4];
    #pragma unroll
    for (int g = 0; g < 4; g++) {
        const float dx = y[g].x - m[g].x;
        const float dy = y[g].y - m[g].y;
        const float dz = y[g].z - m[g].z;
        const float dw = y[g].w - m[g].w;
        const float pxy = s[g].x * s[g].y;
        const float pzw = s[g].z * s[g].w;
        const float nxy = dx * dx * s[g].y + dy * dy * s[g].x;
        const float nzw = dz * dz * s[g].w + dw * dw * s[g].z;
        num4[g] = nxy * pzw + nzw * pxy;
        p4[g]   = pxy * pzw;
    }

    // Fold 4 -> 2 -> 1 (common-denominator tree).
    const float num8_0 = num4[0] * p4[1] + num4[1] * p4[0];
    const float p8_0   = p4[0] * p4[1];
    const float num8_1 = num4[2] * p4[3] + num4[3] * p4[2];
    const float p8_1   = p4[2] * p4[3];
    const float num16  = num8_0 * p8_1 + num8_1 * p8_0;
    const float p16    = p8_0 * p8_1;

    // ONE division + ONE log per thread.
    float acc = __fdividef(num16, p16) + __logf(p16);

    // per-warp reduce (SHFL butterfly)
    #pragma unroll
    for (int off = 16; off > 0; off >>= 1)
        acc += __shfl_xor_sync(0xFFFFFFFFu, acc, off);

    __shared__ __align__(16) float warp_sums[THREADS / 32];  // 4 floats, 16B
    const int wid = tid >> 5;
    const int lid = tid & 31;
    if (lid == 0) warp_sums[wid] = acc;
    __syncthreads();

    if (tid == 0) {
        // single LDS.128 gathers all 4 warp partials; local serial sum
        const float4 ws = *reinterpret_cast<const float4*>(warp_sums);
        const float v = (ws.x + ws.y) + (ws.z + ws.w);
        const float LOG_2PI = 1.8378770664093453f;
        const float INV_SCALE = 0.5f / ((float)NT * (float)BS);
        out[0] = (v + (float)NT * LOG_2PI) * INV_SCALE;
    }
}

extern "C" void kernel_launch(void* const* d_in, const int* in_sizes, int n_in,
                              void* d_out, int out_size) {
    const float* mu    = (const float*)d_in[0];
    const float* sigma = (const float*)d_in[1];
    const float* ty    = (const float*)d_in[2];
    float* out = (float*)d_out;
    criterion_last_row_kernel<<<1, THREADS>>>(mu, sigma, ty, out);
}